// round 1
// baseline (speedup 1.0000x reference)
#include <cuda_runtime.h>

#define SQ 2048
#define DM 1024
#define NH 16
#define HD 64

// Scratch (allocation-free): Q, K, V projections and attention output O.
__device__ float g_q[SQ * DM];
__device__ float g_k[SQ * DM];
__device__ float g_v[SQ * DM];
__device__ float g_o[SQ * DM];

// ---------------------------------------------------------------------------
// Generic tiled fp32 GEMM, 64x64 tile, BK=16, 256 threads, 4x4 per thread.
// BT=1: C[m,n] = sum_k A[m*lda+k] * B[n*ldb+k]   (B transposed, K-major)
// BT=0: C[m,n] = sum_k A[m*lda+k] * B[k*ldb+n]   (B normal, N-major)
// blockIdx.z applies per-slice pointer offsets (for per-head batching).
// ---------------------------------------------------------------------------
template <int BT>
__global__ void gemm64(const float* __restrict__ A, const float* __restrict__ B,
                       float* __restrict__ C, int K, int lda, int ldb, int ldc,
                       int azs, int bzs, int czs) {
    A += (long long)blockIdx.z * azs;
    B += (long long)blockIdx.z * bzs;
    C += (long long)blockIdx.z * czs;

    __shared__ float As[16][65];
    __shared__ float Bs[16][65];

    const int tid = threadIdx.x;
    const int tx = tid & 15, ty = tid >> 4;
    const int m0 = blockIdx.y * 64, n0 = blockIdx.x * 64;

    float acc[4][4] = {};

    for (int k0 = 0; k0 < K; k0 += 16) {
#pragma unroll
        for (int i = 0; i < 4; i++) {
            int e = tid + i * 256;
            int r = e >> 4, c = e & 15;
            As[c][r] = A[(m0 + r) * lda + k0 + c];
        }
#pragma unroll
        for (int i = 0; i < 4; i++) {
            int e = tid + i * 256;
            if (BT) {
                int r = e >> 4, c = e & 15;
                Bs[c][r] = B[(n0 + r) * ldb + k0 + c];
            } else {
                int kk = e >> 6, n = e & 63;
                Bs[kk][n] = B[(k0 + kk) * ldb + n0 + n];
            }
        }
        __syncthreads();
#pragma unroll
        for (int kk = 0; kk < 16; kk++) {
            float a[4], b[4];
#pragma unroll
            for (int i = 0; i < 4; i++) a[i] = As[kk][ty * 4 + i];
#pragma unroll
            for (int j = 0; j < 4; j++) b[j] = Bs[kk][tx * 4 + j];
#pragma unroll
            for (int i = 0; i < 4; i++)
#pragma unroll
                for (int j = 0; j < 4; j++) acc[i][j] += a[i] * b[j];
        }
        __syncthreads();
    }

#pragma unroll
    for (int i = 0; i < 4; i++)
#pragma unroll
        for (int j = 0; j < 4; j++)
            C[(long long)(m0 + ty * 4 + i) * ldc + n0 + tx * 4 + j] = acc[i][j];
}

// ---------------------------------------------------------------------------
// scores[h,s,t] = mask[s,t] ? -1e-7 : (q_h[s,:] . k_h[t,:]) / 8
// Written PRE-softmax into the attn region of d_out (doubles as scratch for
// the scores@V GEMM, per the reference's pre-softmax quirk).
// ---------------------------------------------------------------------------
__global__ void scores_kernel(const float* __restrict__ q, const float* __restrict__ k,
                              const int* __restrict__ mask, float* __restrict__ attn) {
    const int h = blockIdx.z;
    const float* A = q + h * HD;  // lda = DM
    const float* B = k + h * HD;  // ldb = DM
    float* Cc = attn + (size_t)h * SQ * SQ;

    __shared__ float As[16][65];
    __shared__ float Bs[16][65];

    const int tid = threadIdx.x;
    const int tx = tid & 15, ty = tid >> 4;
    const int m0 = blockIdx.y * 64, n0 = blockIdx.x * 64;

    float acc[4][4] = {};

    for (int k0 = 0; k0 < HD; k0 += 16) {
#pragma unroll
        for (int i = 0; i < 4; i++) {
            int e = tid + i * 256;
            int r = e >> 4, c = e & 15;
            As[c][r] = A[(m0 + r) * DM + k0 + c];
            Bs[c][r] = B[(n0 + r) * DM + k0 + c];
        }
        __syncthreads();
#pragma unroll
        for (int kk = 0; kk < 16; kk++) {
            float a[4], b[4];
#pragma unroll
            for (int i = 0; i < 4; i++) a[i] = As[kk][ty * 4 + i];
#pragma unroll
            for (int j = 0; j < 4; j++) b[j] = Bs[kk][tx * 4 + j];
#pragma unroll
            for (int i = 0; i < 4; i++)
#pragma unroll
                for (int j = 0; j < 4; j++) acc[i][j] += a[i] * b[j];
        }
        __syncthreads();
    }

#pragma unroll
    for (int i = 0; i < 4; i++) {
        int s = m0 + ty * 4 + i;
#pragma unroll
        for (int j = 0; j < 4; j++) {
            int t = n0 + tx * 4 + j;
            float v = acc[i][j] * 0.125f;
            if (mask[s * SQ + t]) v = -1e-7f;
            Cc[(size_t)s * SQ + t] = v;
        }
    }
}

// ---------------------------------------------------------------------------
// In-place row softmax over the last axis (2048) of attn [H, S, S].
// One block per row, 256 threads, 8 elements per thread.
// ---------------------------------------------------------------------------
__global__ void softmax_kernel(float* __restrict__ attn) {
    __shared__ float red[8];
    const size_t base = (size_t)blockIdx.x * SQ;
    const int tid = threadIdx.x;

    float v[8];
    float m = -1e30f;
#pragma unroll
    for (int i = 0; i < 8; i++) {
        v[i] = attn[base + tid + i * 256];
        m = fmaxf(m, v[i]);
    }
#pragma unroll
    for (int o = 16; o; o >>= 1) m = fmaxf(m, __shfl_xor_sync(0xffffffffu, m, o));
    if ((tid & 31) == 0) red[tid >> 5] = m;
    __syncthreads();
    float mm = red[0];
#pragma unroll
    for (int w = 1; w < 8; w++) mm = fmaxf(mm, red[w]);

    float s = 0.f;
#pragma unroll
    for (int i = 0; i < 8; i++) {
        v[i] = expf(v[i] - mm);
        s += v[i];
    }
#pragma unroll
    for (int o = 16; o; o >>= 1) s += __shfl_xor_sync(0xffffffffu, s, o);
    __syncthreads();  // everyone done reading maxes before red is reused
    if ((tid & 31) == 0) red[tid >> 5] = s;
    __syncthreads();
    float ss = 0.f;
#pragma unroll
    for (int w = 0; w < 8; w++) ss += red[w];
    const float inv = 1.0f / ss;
#pragma unroll
    for (int i = 0; i < 8; i++) attn[base + tid + i * 256] = v[i] * inv;
}

// ---------------------------------------------------------------------------
// Launch: 3 projections -> masked pre-softmax scores (into d_out attn region)
//         -> O = scores @ V -> softmax(attn) in place -> out = O @ W_o^T
// ---------------------------------------------------------------------------
extern "C" void kernel_launch(void* const* d_in, const int* in_sizes, int n_in,
                              void* d_out, int out_size) {
    const float* q_in = (const float*)d_in[0];
    const float* k_in = (const float*)d_in[1];
    const float* v_in = (const float*)d_in[2];
    const int* mask = (const int*)d_in[3];
    const float* Wq = (const float*)d_in[4];
    const float* Wk = (const float*)d_in[5];
    const float* Wv = (const float*)d_in[6];
    const float* Wo = (const float*)d_in[7];

    float* out = (float*)d_out;               // [S, DM]
    float* attn = out + (size_t)SQ * DM;      // [H, S, S]

    float *gq, *gk, *gv, *go;
    cudaGetSymbolAddress((void**)&gq, g_q);
    cudaGetSymbolAddress((void**)&gk, g_k);
    cudaGetSymbolAddress((void**)&gv, g_v);
    cudaGetSymbolAddress((void**)&go, g_o);

    dim3 gProj(DM / 64, SQ / 64, 1);  // (16, 32)
    gemm64<1><<<gProj, 256>>>(q_in, Wq, gq, DM, DM, DM, DM, 0, 0, 0);
    gemm64<1><<<gProj, 256>>>(k_in, Wk, gk, DM, DM, DM, DM, 0, 0, 0);
    gemm64<1><<<gProj, 256>>>(v_in, Wv, gv, DM, DM, DM, DM, 0, 0, 0);

    dim3 gScores(SQ / 64, SQ / 64, NH);  // (32, 32, 16)
    scores_kernel<<<gScores, 256>>>(gq, gk, mask, attn);

    // O_h = scores_h @ V_h : per-head NN GEMM, M=S, N=HD, K=S
    dim3 gAV(HD / 64, SQ / 64, NH);  // (1, 32, 16)
    gemm64<0><<<gAV, 256>>>(attn, gv, go, SQ, SQ, DM, DM, SQ * SQ, HD, HD);

    softmax_kernel<<<NH * SQ, 256>>>(attn);

    gemm64<1><<<gProj, 256>>>(go, Wo, out, DM, DM, DM, DM, 0, 0, 0);
}

// round 2
// speedup vs baseline: 2.5780x; 2.5780x over previous
#include <cuda_runtime.h>
#include <cstdint>

#define SQ 2048
#define DM 1024
#define NH 16
#define HD 64

#define BM 128
#define BKT 32

// Scratch (allocation-free): Q, K, V projections and attention output O.
__device__ float g_q[SQ * DM];
__device__ float g_k[SQ * DM];
__device__ float g_v[SQ * DM];
__device__ float g_o[SQ * DM];

__device__ __forceinline__ uint32_t f2tf(float f) {
    uint32_t u;
    asm("cvt.rna.tf32.f32 %0, %1;" : "=r"(u) : "f"(f));
    return u;
}

__device__ __forceinline__ void mma8(float* c, uint32_t a0, uint32_t a1, uint32_t a2,
                                     uint32_t a3, uint32_t b0, uint32_t b1) {
    asm("mma.sync.aligned.m16n8k8.row.col.f32.tf32.tf32.f32 "
        "{%0,%1,%2,%3},{%4,%5,%6,%7},{%8,%9},{%0,%1,%2,%3};"
        : "+f"(c[0]), "+f"(c[1]), "+f"(c[2]), "+f"(c[3])
        : "r"(a0), "r"(a1), "r"(a2), "r"(a3), "r"(b0), "r"(b1));
}

// ---------------------------------------------------------------------------
// tf32 tensor-core GEMM. BM=128, BK=32, 256 threads (8 warps, 2x4).
// BT=1: C[m,n] = sum_k A[m,k] * B[n,k]   (B K-major)
// BT=0: C[m,n] = sum_k A[m,k] * B[k,n]   (B N-major)
// EPI=1: v = acc/8, masked_fill(-1e-7), C = v  (pre-softmax scores)
// blockIdx.z applies per-head pointer offsets.
// ---------------------------------------------------------------------------
template <int BN, int BT, int EPI>
__global__ __launch_bounds__(256) void gemm_mma(
    const float* __restrict__ A, const float* __restrict__ B, float* __restrict__ C,
    const int* __restrict__ mask, int K, int lda, int ldb, int ldc,
    long long azs, long long bzs, long long czs) {
    A += blockIdx.z * azs;
    B += blockIdx.z * bzs;
    C += blockIdx.z * czs;

    constexpr int NF = BN / 32;                       // n-frags per warp
    constexpr int BSZ = BT ? BN * 36 : BKT * (BN + 8);
    __shared__ __align__(16) uint32_t As[BM * 36];    // [m][k], stride 36
    __shared__ __align__(16) uint32_t Bs[BSZ];        // BT=1: [n][36]; BT=0: [k][BN+8]

    const int tid = threadIdx.x;
    const int lane = tid & 31;
    const int wid = tid >> 5;
    const int wm = (wid & 1) * 64;          // warp m offset
    const int wn = (wid >> 1) * (BN / 4);   // warp n offset
    const int g = lane >> 2;                // group id (0..7)
    const int t4 = lane & 3;                // thread-in-group (0..3)
    const int m0 = blockIdx.y * BM, n0 = blockIdx.x * BN;

    float acc[4][NF][4] = {};

    for (int k0 = 0; k0 < K; k0 += BKT) {
        // --- stage A tile [BM x 32] -> As[m][k] ---
#pragma unroll
        for (int i = 0; i < 4; i++) {
            int idx = tid + i * 256;
            int row = idx >> 3, col = (idx & 7) * 4;
            float4 v = *(const float4*)(A + (long long)(m0 + row) * lda + k0 + col);
            uint4 u = {f2tf(v.x), f2tf(v.y), f2tf(v.z), f2tf(v.w)};
            *(uint4*)(As + row * 36 + col) = u;
        }
        // --- stage B tile ---
        if (BT) {  // B[n][k] -> Bs[n][k], stride 36
#pragma unroll
            for (int i = 0; i < BN * BKT / 1024; i++) {
                int idx = tid + i * 256;
                int row = idx >> 3, col = (idx & 7) * 4;
                float4 v = *(const float4*)(B + (long long)(n0 + row) * ldb + k0 + col);
                uint4 u = {f2tf(v.x), f2tf(v.y), f2tf(v.z), f2tf(v.w)};
                *(uint4*)(Bs + row * 36 + col) = u;
            }
        } else {  // B[k][n] -> Bs[k][n], stride BN+8
#pragma unroll
            for (int i = 0; i < BN * BKT / 1024; i++) {
                int idx = tid + i * 256;
                int row = idx / (BN / 4), col = (idx % (BN / 4)) * 4;
                float4 v = *(const float4*)(B + (long long)(k0 + row) * ldb + n0 + col);
                uint4 u = {f2tf(v.x), f2tf(v.y), f2tf(v.z), f2tf(v.w)};
                *(uint4*)(Bs + row * (BN + 8) + col) = u;
            }
        }
        __syncthreads();

#pragma unroll
        for (int ks = 0; ks < BKT; ks += 8) {
            uint32_t a[4][4];
#pragma unroll
            for (int mi = 0; mi < 4; mi++) {
                int base = (wm + mi * 16 + g) * 36 + ks + t4;
                a[mi][0] = As[base];
                a[mi][1] = As[base + 8 * 36];
                a[mi][2] = As[base + 4];
                a[mi][3] = As[base + 8 * 36 + 4];
            }
            uint32_t b[NF][2];
#pragma unroll
            for (int ni = 0; ni < NF; ni++) {
                if (BT) {
                    int base = (wn + ni * 8 + g) * 36 + ks + t4;
                    b[ni][0] = Bs[base];
                    b[ni][1] = Bs[base + 4];
                } else {
                    int base = (ks + t4) * (BN + 8) + wn + ni * 8 + g;
                    b[ni][0] = Bs[base];
                    b[ni][1] = Bs[base + 4 * (BN + 8)];
                }
            }
#pragma unroll
            for (int mi = 0; mi < 4; mi++)
#pragma unroll
                for (int ni = 0; ni < NF; ni++)
                    mma8(acc[mi][ni], a[mi][0], a[mi][1], a[mi][2], a[mi][3],
                         b[ni][0], b[ni][1]);
        }
        __syncthreads();
    }

    // --- epilogue ---
#pragma unroll
    for (int mi = 0; mi < 4; mi++) {
#pragma unroll
        for (int ni = 0; ni < NF; ni++) {
#pragma unroll
            for (int e = 0; e < 4; e++) {
                int row = m0 + wm + mi * 16 + g + (e >> 1) * 8;
                int col = n0 + wn + ni * 8 + t4 * 2 + (e & 1);
                float v = acc[mi][ni][e];
                if (EPI) {
                    v *= 0.125f;
                    if (mask[(long long)row * SQ + col]) v = -1e-7f;
                }
                C[(long long)row * ldc + col] = v;
            }
        }
    }
}

// ---------------------------------------------------------------------------
// In-place row softmax over the last axis (2048) of attn [H, S, S].
// ---------------------------------------------------------------------------
__global__ void softmax_kernel(float* __restrict__ attn) {
    __shared__ float red[8];
    const size_t base = (size_t)blockIdx.x * SQ;
    const int tid = threadIdx.x;

    float v[8];
    float m = -1e30f;
#pragma unroll
    for (int i = 0; i < 8; i++) {
        v[i] = attn[base + tid + i * 256];
        m = fmaxf(m, v[i]);
    }
#pragma unroll
    for (int o = 16; o; o >>= 1) m = fmaxf(m, __shfl_xor_sync(0xffffffffu, m, o));
    if ((tid & 31) == 0) red[tid >> 5] = m;
    __syncthreads();
    float mm = red[0];
#pragma unroll
    for (int w = 1; w < 8; w++) mm = fmaxf(mm, red[w]);

    float s = 0.f;
#pragma unroll
    for (int i = 0; i < 8; i++) {
        v[i] = expf(v[i] - mm);
        s += v[i];
    }
#pragma unroll
    for (int o = 16; o; o >>= 1) s += __shfl_xor_sync(0xffffffffu, s, o);
    __syncthreads();
    if ((tid & 31) == 0) red[tid >> 5] = s;
    __syncthreads();
    float ss = 0.f;
#pragma unroll
    for (int w = 0; w < 8; w++) ss += red[w];
    const float inv = 1.0f / ss;
#pragma unroll
    for (int i = 0; i < 8; i++) attn[base + tid + i * 256] = v[i] * inv;
}

extern "C" void kernel_launch(void* const* d_in, const int* in_sizes, int n_in,
                              void* d_out, int out_size) {
    const float* q_in = (const float*)d_in[0];
    const float* k_in = (const float*)d_in[1];
    const float* v_in = (const float*)d_in[2];
    const int* mask = (const int*)d_in[3];
    const float* Wq = (const float*)d_in[4];
    const float* Wk = (const float*)d_in[5];
    const float* Wv = (const float*)d_in[6];
    const float* Wo = (const float*)d_in[7];

    float* out = (float*)d_out;           // [S, DM]
    float* attn = out + (size_t)SQ * DM;  // [H, S, S]

    float *gq, *gk, *gv, *go;
    cudaGetSymbolAddress((void**)&gq, g_q);
    cudaGetSymbolAddress((void**)&gk, g_k);
    cudaGetSymbolAddress((void**)&gv, g_v);
    cudaGetSymbolAddress((void**)&go, g_o);

    // Projections: [S,DM] @ W^T -> [S,DM]
    dim3 gProj(DM / 128, SQ / 128, 1);  // (8, 16)
    gemm_mma<128, 1, 0><<<gProj, 256>>>(q_in, Wq, gq, nullptr, DM, DM, DM, DM, 0, 0, 0);
    gemm_mma<128, 1, 0><<<gProj, 256>>>(k_in, Wk, gk, nullptr, DM, DM, DM, DM, 0, 0, 0);
    gemm_mma<128, 1, 0><<<gProj, 256>>>(v_in, Wv, gv, nullptr, DM, DM, DM, DM, 0, 0, 0);

    // Masked pre-softmax scores into attn region of d_out (scratch + output)
    dim3 gScores(SQ / 128, SQ / 128, NH);  // (16, 16, 16)
    gemm_mma<128, 1, 1><<<gScores, 256>>>(gq, gk, attn, mask, HD, DM, DM, SQ,
                                          HD, HD, (long long)SQ * SQ);

    // O_h = scores_h @ V_h  (N=64 per head, B is N-major)
    dim3 gAV(1, SQ / 128, NH);  // (1, 16, 16)
    gemm_mma<64, 0, 0><<<gAV, 256>>>(attn, gv, go, nullptr, SQ, SQ, DM, DM,
                                     (long long)SQ * SQ, HD, HD);

    // Softmax attn in place (the attn_scores output)
    softmax_kernel<<<NH * SQ, 256>>>(attn);

    // Output projection
    gemm_mma<128, 1, 0><<<gProj, 256>>>(go, Wo, out, nullptr, DM, DM, DM, DM, 0, 0, 0);
}

// round 3
// speedup vs baseline: 2.8230x; 1.0950x over previous
#include <cuda_runtime.h>
#include <cstdint>

#define SQ 2048
#define DM 1024
#define NH 16
#define HD 64

// Scratch (allocation-free)
__device__ float g_q[SQ * DM];    // Q projection (tf32-rounded), [s][h*64+n]
__device__ float g_k[SQ * DM];    // K projection (tf32-rounded)
__device__ float g_vT[DM * SQ];   // V projection TRANSPOSED (tf32-rounded): [h*64+n][t]
__device__ float g_o[SQ * DM];    // attention output O (fp32)

__device__ __forceinline__ uint32_t f2tf(float f) {
    uint32_t u;
    asm("cvt.rna.tf32.f32 %0, %1;" : "=r"(u) : "f"(f));
    return u;
}

__device__ __forceinline__ void mma8(float* c, uint32_t a0, uint32_t a1, uint32_t a2,
                                     uint32_t a3, uint32_t b0, uint32_t b1) {
    asm("mma.sync.aligned.m16n8k8.row.col.f32.tf32.tf32.f32 "
        "{%0,%1,%2,%3},{%4,%5,%6,%7},{%8,%9},{%0,%1,%2,%3};"
        : "+f"(c[0]), "+f"(c[1]), "+f"(c[2]), "+f"(c[3])
        : "r"(a0), "r"(a1), "r"(a2), "r"(a3), "r"(b0), "r"(b1));
}

// ---------------------------------------------------------------------------
// Permuted ("fragment-major") smem layout. For a tile X[R][K] (K-major, K a
// multiple of 8, NS = K/8 k-steps), element (r,k) lives at:
//   band=r>>4, g=r&7, hm=(r>>3)&1, s=k>>3, kk=k&7, hk=kk>>2
//   L = g*4 + ((kk&3) ^ (g&3))        <- XOR swizzle spreads staging banks
//   word = ((band*NS + s)*32 + L)*4 + hm + 2*hk
// Then lane (g,t4) of a warp fetches its whole m16n8k8 a-frag (a0,a1,a2,a3)
// (or a 2-frag b pair) with ONE LDS.128 at ((band*NS+s)*32 + g*4+(t4^(g&3)))*4.
// ---------------------------------------------------------------------------
__device__ __forceinline__ int perm_word(int NS, int r, int k) {
    int gg = r & 7;
    int kk = k & 7;
    int L = gg * 4 + ((kk & 3) ^ (gg & 3));
    return (((r >> 4) * NS + (k >> 3)) * 32 + L) * 4 + ((r >> 3) & 1) + 2 * (kk >> 2);
}

// store 4 consecutive-k words (r, c4..c4+3), c4 % 4 == 0
__device__ __forceinline__ void sts_perm4(uint32_t* S, int NS, int r, int c4, uint4 u) {
    int gg = r & 7;
    int base = (((r >> 4) * NS + (c4 >> 3)) * 32 + gg * 4) * 4 + ((r >> 3) & 1) +
               2 * ((c4 >> 2) & 1);
    int x = gg & 3;
    S[base + (0 ^ x) * 4] = u.x;
    S[base + (1 ^ x) * 4] = u.y;
    S[base + (2 ^ x) * 4] = u.z;
    S[base + (3 ^ x) * 4] = u.w;
}

__device__ __forceinline__ int frag_addr(int NS, int band, int s, int g, int t4) {
    return ((band * NS + s) * 32 + g * 4 + (t4 ^ (g & 3))) * 4;
}

// ---------------------------------------------------------------------------
// Projection GEMM: C[m][n] = sum_k A[m][k]*B[n][k], M=2048, N=1024, K=1024.
// BM=128, BN=64, BK=32. 8 warps (2 m-groups x 4 n-groups). LDS.128 frags.
// CVT=1: round result to tf32 before store. TRANSC=1: store C[n][m] (ld SQ).
// ---------------------------------------------------------------------------
template <int TRANSC, int CVT>
__global__ __launch_bounds__(256) void gemm_p(const float* __restrict__ A,
                                              const float* __restrict__ B,
                                              float* __restrict__ C) {
    __shared__ uint32_t Ap[4096];  // 128 x 32, NS=4
    __shared__ uint32_t Bp[2048];  // 64 x 32, NS=4
    const int tid = threadIdx.x, lane = tid & 31, wid = tid >> 5;
    const int g = lane >> 2, t4 = lane & 3;
    const int wm = (wid & 1) * 64, wn = (wid >> 1) * 16;
    const int m0 = blockIdx.y * 128, n0 = blockIdx.x * 64;

    float acc[4][2][4] = {};
    float4 pa[4], pb[2];

    // prefetch tile 0
#pragma unroll
    for (int i = 0; i < 4; i++) {
        int idx = tid + i * 256, r = idx >> 3, c4 = (idx & 7) * 4;
        pa[i] = *(const float4*)(A + (m0 + r) * DM + c4);
    }
#pragma unroll
    for (int i = 0; i < 2; i++) {
        int idx = tid + i * 256, r = idx >> 3, c4 = (idx & 7) * 4;
        pb[i] = *(const float4*)(B + (n0 + r) * DM + c4);
    }

    for (int kt = 0; kt < DM / 32; kt++) {
#pragma unroll
        for (int i = 0; i < 4; i++) {
            int idx = tid + i * 256, r = idx >> 3, c4 = (idx & 7) * 4;
            uint4 u = {f2tf(pa[i].x), f2tf(pa[i].y), f2tf(pa[i].z), f2tf(pa[i].w)};
            sts_perm4(Ap, 4, r, c4, u);
        }
#pragma unroll
        for (int i = 0; i < 2; i++) {
            int idx = tid + i * 256, r = idx >> 3, c4 = (idx & 7) * 4;
            uint4 u = {f2tf(pb[i].x), f2tf(pb[i].y), f2tf(pb[i].z), f2tf(pb[i].w)};
            sts_perm4(Bp, 4, r, c4, u);
        }
        __syncthreads();
        if (kt + 1 < DM / 32) {
            int k0 = (kt + 1) * 32;
#pragma unroll
            for (int i = 0; i < 4; i++) {
                int idx = tid + i * 256, r = idx >> 3, c4 = (idx & 7) * 4;
                pa[i] = *(const float4*)(A + (m0 + r) * DM + k0 + c4);
            }
#pragma unroll
            for (int i = 0; i < 2; i++) {
                int idx = tid + i * 256, r = idx >> 3, c4 = (idx & 7) * 4;
                pb[i] = *(const float4*)(B + (n0 + r) * DM + k0 + c4);
            }
        }
#pragma unroll
        for (int s = 0; s < 4; s++) {
            uint4 av[4];
#pragma unroll
            for (int mi = 0; mi < 4; mi++)
                av[mi] = *(const uint4*)&Ap[frag_addr(4, (wm >> 4) + mi, s, g, t4)];
            uint4 bv = *(const uint4*)&Bp[frag_addr(4, wn >> 4, s, g, t4)];
#pragma unroll
            for (int mi = 0; mi < 4; mi++) {
                mma8(acc[mi][0], av[mi].x, av[mi].y, av[mi].z, av[mi].w, bv.x, bv.z);
                mma8(acc[mi][1], av[mi].x, av[mi].y, av[mi].z, av[mi].w, bv.y, bv.w);
            }
        }
        __syncthreads();
    }

#pragma unroll
    for (int mi = 0; mi < 4; mi++)
#pragma unroll
        for (int ni = 0; ni < 2; ni++)
#pragma unroll
            for (int e = 0; e < 4; e++) {
                int row = m0 + wm + mi * 16 + g + (e >> 1) * 8;
                int col = n0 + wn + ni * 8 + t4 * 2 + (e & 1);
                float v = acc[mi][ni][e];
                if (CVT) v = __uint_as_float(f2tf(v));
                if (TRANSC)
                    C[col * SQ + row] = v;
                else
                    C[row * DM + col] = v;
            }
}

// ---------------------------------------------------------------------------
// Fused attention: per (head, 128-row block), loop over 32 column tiles of 64:
//   S = (Q K^T)/8, masked_fill -> write pre-softmax S to attn (d_out region)
//   O += S @ V  (S routed through smem as tf32 A-frags; V^T staged K-major)
// 3 syncthreads per tile. Smem 96KB dynamic -> 2 blocks/SM, 256 blocks = 1 wave.
// ---------------------------------------------------------------------------
__global__ __launch_bounds__(256, 2) void fused_attn(
    const float* __restrict__ gq, const float* __restrict__ gk,
    const float* __restrict__ gvT, const int* __restrict__ mask,
    float* __restrict__ attn, float* __restrict__ go) {
    extern __shared__ uint32_t sm[];
    uint32_t* Qp = sm;           // 128 x 64, NS=8 -> 8192 w
    uint32_t* Kp = sm + 8192;    // 64 x 64,  NS=8 -> 4096 w
    uint32_t* Vp = sm + 12288;   // 64(n) x 64(t), NS=8 -> 4096 w
    uint32_t* Sp = sm + 16384;   // 128 x 64, NS=8 -> 8192 w

    const int tid = threadIdx.x, lane = tid & 31, wid = tid >> 5;
    const int g = lane >> 2, t4 = lane & 3;
    const int wm = (wid & 1) * 64, wn = (wid >> 1) * 16;
    const int h = blockIdx.y;
    const int m0 = blockIdx.x * 128;
    const size_t attn_base = (size_t)h * SQ * SQ;

    // stage Q once (values already tf32-rounded by projection)
#pragma unroll
    for (int i = 0; i < 8; i++) {
        int idx = tid + i * 256, r = idx >> 4, c4 = (idx & 15) * 4;
        float4 v = *(const float4*)(gq + (m0 + r) * DM + h * HD + c4);
        uint4 u = {__float_as_uint(v.x), __float_as_uint(v.y), __float_as_uint(v.z),
                   __float_as_uint(v.w)};
        sts_perm4(Qp, 8, r, c4, u);
    }

    float oacc[4][2][4] = {};

    for (int tt = 0; tt < SQ / 64; tt++) {
        const int t0 = tt * 64;
        __syncthreads();  // prev tile fully consumed (also publishes Qp on tt=0)

        // stage K tile (rows t0..t0+63 of K) and V^T tile (64 n x 64 t)
#pragma unroll
        for (int i = 0; i < 4; i++) {
            int idx = tid + i * 256, r = idx >> 4, c4 = (idx & 15) * 4;
            float4 v = *(const float4*)(gk + (t0 + r) * DM + h * HD + c4);
            uint4 u = {__float_as_uint(v.x), __float_as_uint(v.y), __float_as_uint(v.z),
                       __float_as_uint(v.w)};
            sts_perm4(Kp, 8, r, c4, u);
            float4 w = *(const float4*)(gvT + (h * HD + r) * SQ + t0 + c4);
            uint4 uw = {__float_as_uint(w.x), __float_as_uint(w.y), __float_as_uint(w.z),
                        __float_as_uint(w.w)};
            sts_perm4(Vp, 8, r, c4, uw);
        }
        __syncthreads();

        // S = Q K^T over 8 k-steps
        float sacc[4][2][4] = {};
#pragma unroll
        for (int s = 0; s < 8; s++) {
            uint4 aq[4];
#pragma unroll
            for (int mi = 0; mi < 4; mi++)
                aq[mi] = *(const uint4*)&Qp[frag_addr(8, (wm >> 4) + mi, s, g, t4)];
            uint4 bk = *(const uint4*)&Kp[frag_addr(8, wn >> 4, s, g, t4)];
#pragma unroll
            for (int mi = 0; mi < 4; mi++) {
                mma8(sacc[mi][0], aq[mi].x, aq[mi].y, aq[mi].z, aq[mi].w, bk.x, bk.z);
                mma8(sacc[mi][1], aq[mi].x, aq[mi].y, aq[mi].z, aq[mi].w, bk.y, bk.w);
            }
        }

        // epilogue: scale + mask, write pre-softmax S to global, stage Sp (tf32)
#pragma unroll
        for (int mi = 0; mi < 4; mi++)
#pragma unroll
            for (int ni = 0; ni < 2; ni++)
#pragma unroll
                for (int e2 = 0; e2 < 2; e2++) {
                    int rl = wm + mi * 16 + g + e2 * 8;
                    int cl = wn + ni * 8 + t4 * 2;
                    int rg = m0 + rl, cg = t0 + cl;
                    int2 mk = *(const int2*)(mask + (size_t)rg * SQ + cg);
                    float v0 = sacc[mi][ni][e2 * 2] * 0.125f;
                    float v1 = sacc[mi][ni][e2 * 2 + 1] * 0.125f;
                    if (mk.x) v0 = -1e-7f;
                    if (mk.y) v1 = -1e-7f;
                    *(float2*)(attn + attn_base + (size_t)rg * SQ + cg) =
                        make_float2(v0, v1);
                    Sp[perm_word(8, rl, cl)] = f2tf(v0);
                    Sp[perm_word(8, rl, cl + 1)] = f2tf(v1);
                }
        __syncthreads();

        // O += S @ V  (A = Sp [128 x 64], B = Vp [64n x 64k])
#pragma unroll
        for (int s = 0; s < 8; s++) {
            uint4 as[4];
#pragma unroll
            for (int mi = 0; mi < 4; mi++)
                as[mi] = *(const uint4*)&Sp[frag_addr(8, (wm >> 4) + mi, s, g, t4)];
            uint4 bv = *(const uint4*)&Vp[frag_addr(8, wn >> 4, s, g, t4)];
#pragma unroll
            for (int mi = 0; mi < 4; mi++) {
                mma8(oacc[mi][0], as[mi].x, as[mi].y, as[mi].z, as[mi].w, bv.x, bv.z);
                mma8(oacc[mi][1], as[mi].x, as[mi].y, as[mi].z, as[mi].w, bv.y, bv.w);
            }
        }
    }

    // write O to g_o[s][h*64+n]
#pragma unroll
    for (int mi = 0; mi < 4; mi++)
#pragma unroll
        for (int ni = 0; ni < 2; ni++)
#pragma unroll
            for (int e = 0; e < 4; e++) {
                int row = m0 + wm + mi * 16 + g + (e >> 1) * 8;
                int col = wn + ni * 8 + t4 * 2 + (e & 1);
                go[row * DM + h * HD + col] = oacc[mi][ni][e];
            }
}

// ---------------------------------------------------------------------------
// In-place row softmax over the last axis (2048) of attn [H, S, S].
// ---------------------------------------------------------------------------
__global__ void softmax_kernel(float* __restrict__ attn) {
    __shared__ float red[8];
    const size_t base = (size_t)blockIdx.x * SQ;
    const int tid = threadIdx.x;

    float v[8];
    float m = -1e30f;
#pragma unroll
    for (int i = 0; i < 8; i++) {
        v[i] = attn[base + tid + i * 256];
        m = fmaxf(m, v[i]);
    }
#pragma unroll
    for (int o = 16; o; o >>= 1) m = fmaxf(m, __shfl_xor_sync(0xffffffffu, m, o));
    if ((tid & 31) == 0) red[tid >> 5] = m;
    __syncthreads();
    float mm = red[0];
#pragma unroll
    for (int w = 1; w < 8; w++) mm = fmaxf(mm, red[w]);

    float s = 0.f;
#pragma unroll
    for (int i = 0; i < 8; i++) {
        v[i] = expf(v[i] - mm);
        s += v[i];
    }
#pragma unroll
    for (int o = 16; o; o >>= 1) s += __shfl_xor_sync(0xffffffffu, s, o);
    __syncthreads();
    if ((tid & 31) == 0) red[tid >> 5] = s;
    __syncthreads();
    float ss = 0.f;
#pragma unroll
    for (int w = 0; w < 8; w++) ss += red[w];
    const float inv = 1.0f / ss;
#pragma unroll
    for (int i = 0; i < 8; i++) attn[base + tid + i * 256] = v[i] * inv;
}

extern "C" void kernel_launch(void* const* d_in, const int* in_sizes, int n_in,
                              void* d_out, int out_size) {
    const float* q_in = (const float*)d_in[0];
    const float* k_in = (const float*)d_in[1];
    const float* v_in = (const float*)d_in[2];
    const int* mask = (const int*)d_in[3];
    const float* Wq = (const float*)d_in[4];
    const float* Wk = (const float*)d_in[5];
    const float* Wv = (const float*)d_in[6];
    const float* Wo = (const float*)d_in[7];

    float* out = (float*)d_out;           // [S, DM]
    float* attn = out + (size_t)SQ * DM;  // [H, S, S]

    float *gq, *gk, *gvT, *go;
    cudaGetSymbolAddress((void**)&gq, g_q);
    cudaGetSymbolAddress((void**)&gk, g_k);
    cudaGetSymbolAddress((void**)&gvT, g_vT);
    cudaGetSymbolAddress((void**)&go, g_o);

    static int smem_set = 0;
    if (!smem_set) {
        cudaFuncSetAttribute(fused_attn, cudaFuncAttributeMaxDynamicSharedMemorySize,
                             98304);
        smem_set = 1;
    }

    dim3 gProj(DM / 64, SQ / 128, 1);  // (16, 16)
    gemm_p<0, 1><<<gProj, 256>>>(q_in, Wq, gq);
    gemm_p<0, 1><<<gProj, 256>>>(k_in, Wk, gk);
    gemm_p<1, 1><<<gProj, 256>>>(v_in, Wv, gvT);

    dim3 gFused(SQ / 128, NH, 1);  // (16, 16)
    fused_attn<<<gFused, 256, 98304>>>(gq, gk, gvT, mask, attn, go);

    softmax_kernel<<<NH * SQ, 256>>>(attn);

    gemm_p<0, 0><<<gProj, 256>>>(go, Wo, out);
}

// round 4
// speedup vs baseline: 3.3182x; 1.1754x over previous
#include <cuda_runtime.h>
#include <cstdint>

#define SQ 2048
#define DM 1024
#define NH 16
#define HD 64
#define NT (SQ / 64)  // 32 column tiles

// Scratch (allocation-free)
__device__ float g_o[SQ * DM];                    // attention output O (fp32)
__device__ uint32_t g_qp[NH * 16 * 8192];         // Q, permuted frag layout per (h, mtile)
__device__ uint32_t g_kp[NH * 32 * 4096];         // K, permuted per (h, ttile)
__device__ uint32_t g_vp[NH * 32 * 4096];         // V^T, permuted per (h, ttile)

__device__ __forceinline__ uint32_t f2tf(float f) {
    uint32_t u;
    asm("cvt.rna.tf32.f32 %0, %1;" : "=r"(u) : "f"(f));
    return u;
}

__device__ __forceinline__ void mma8(float* c, uint32_t a0, uint32_t a1, uint32_t a2,
                                     uint32_t a3, uint32_t b0, uint32_t b1) {
    asm("mma.sync.aligned.m16n8k8.row.col.f32.tf32.tf32.f32 "
        "{%0,%1,%2,%3},{%4,%5,%6,%7},{%8,%9},{%0,%1,%2,%3};"
        : "+f"(c[0]), "+f"(c[1]), "+f"(c[2]), "+f"(c[3])
        : "r"(a0), "r"(a1), "r"(a2), "r"(a3), "r"(b0), "r"(b1));
}

// Permuted fragment-major layout (verified in rounds 3): element (r,k) of a
// K-major tile with NS = K/8 k-steps lives at:
__device__ __forceinline__ int perm_word(int NS, int r, int k) {
    int gg = r & 7;
    int kk = k & 7;
    int L = gg * 4 + ((kk & 3) ^ (gg & 3));
    return (((r >> 4) * NS + (k >> 3)) * 32 + L) * 4 + ((r >> 3) & 1) + 2 * (kk >> 2);
}
__device__ __forceinline__ void sts_perm4(uint32_t* S, int NS, int r, int c4, uint4 u) {
    int gg = r & 7;
    int base = (((r >> 4) * NS + (c4 >> 3)) * 32 + gg * 4) * 4 + ((r >> 3) & 1) +
               2 * ((c4 >> 2) & 1);
    int x = gg & 3;
    S[base + (0 ^ x) * 4] = u.x;
    S[base + (1 ^ x) * 4] = u.y;
    S[base + (2 ^ x) * 4] = u.z;
    S[base + (3 ^ x) * 4] = u.w;
}
__device__ __forceinline__ int frag_addr(int NS, int band, int s, int g, int t4) {
    return ((band * NS + s) * 32 + g * 4 + (t4 ^ (g & 3))) * 4;
}

__device__ __forceinline__ void cpa16(void* dst, const void* src) {
    uint32_t s = (uint32_t)__cvta_generic_to_shared(dst);
    asm volatile("cp.async.cg.shared.global [%0], [%1], 16;" ::"r"(s), "l"(src));
}
#define CPA_COMMIT asm volatile("cp.async.commit_group;")
#define CPA_WAIT(n) asm volatile("cp.async.wait_group %0;" ::"n"(n))

// ---------------------------------------------------------------------------
// QKV projections, z-batched (z=0:Q, 1:K, 2:V). C = A @ W^T, tf32-rounded,
// written directly in the permuted fragment layout the fused kernel consumes.
// BM=128, BN=64 (n-block == head), BK=32, 256 threads.
// ---------------------------------------------------------------------------
__global__ __launch_bounds__(256) void gemm_qkv(
    const float* __restrict__ q_in, const float* __restrict__ k_in,
    const float* __restrict__ v_in, const float* __restrict__ Wq,
    const float* __restrict__ Wk, const float* __restrict__ Wv) {
    const int z = blockIdx.z;
    const float* A = z == 0 ? q_in : z == 1 ? k_in : v_in;
    const float* B = z == 0 ? Wq : z == 1 ? Wk : Wv;
    uint32_t* D = z == 0 ? g_qp : z == 1 ? g_kp : g_vp;

    __shared__ uint32_t Ap[4096];  // 128 x 32, NS=4
    __shared__ uint32_t Bp[2048];  // 64 x 32, NS=4
    const int tid = threadIdx.x, lane = tid & 31, wid = tid >> 5;
    const int g = lane >> 2, t4 = lane & 3;
    const int wm = (wid & 1) * 64, wn = (wid >> 1) * 16;
    const int m0 = blockIdx.y * 128, n0 = blockIdx.x * 64;

    float acc[4][2][4] = {};
    float4 pa[4], pb[2];

#pragma unroll
    for (int i = 0; i < 4; i++) {
        int idx = tid + i * 256, r = idx >> 3, c4 = (idx & 7) * 4;
        pa[i] = *(const float4*)(A + (m0 + r) * DM + c4);
    }
#pragma unroll
    for (int i = 0; i < 2; i++) {
        int idx = tid + i * 256, r = idx >> 3, c4 = (idx & 7) * 4;
        pb[i] = *(const float4*)(B + (n0 + r) * DM + c4);
    }

    for (int kt = 0; kt < DM / 32; kt++) {
#pragma unroll
        for (int i = 0; i < 4; i++) {
            int idx = tid + i * 256, r = idx >> 3, c4 = (idx & 7) * 4;
            uint4 u = {f2tf(pa[i].x), f2tf(pa[i].y), f2tf(pa[i].z), f2tf(pa[i].w)};
            sts_perm4(Ap, 4, r, c4, u);
        }
#pragma unroll
        for (int i = 0; i < 2; i++) {
            int idx = tid + i * 256, r = idx >> 3, c4 = (idx & 7) * 4;
            uint4 u = {f2tf(pb[i].x), f2tf(pb[i].y), f2tf(pb[i].z), f2tf(pb[i].w)};
            sts_perm4(Bp, 4, r, c4, u);
        }
        __syncthreads();
        if (kt + 1 < DM / 32) {
            int k0 = (kt + 1) * 32;
#pragma unroll
            for (int i = 0; i < 4; i++) {
                int idx = tid + i * 256, r = idx >> 3, c4 = (idx & 7) * 4;
                pa[i] = *(const float4*)(A + (m0 + r) * DM + k0 + c4);
            }
#pragma unroll
            for (int i = 0; i < 2; i++) {
                int idx = tid + i * 256, r = idx >> 3, c4 = (idx & 7) * 4;
                pb[i] = *(const float4*)(B + (n0 + r) * DM + k0 + c4);
            }
        }
#pragma unroll
        for (int s = 0; s < 4; s++) {
            uint4 av[4];
#pragma unroll
            for (int mi = 0; mi < 4; mi++)
                av[mi] = *(const uint4*)&Ap[frag_addr(4, (wm >> 4) + mi, s, g, t4)];
            uint4 bv = *(const uint4*)&Bp[frag_addr(4, wn >> 4, s, g, t4)];
#pragma unroll
            for (int mi = 0; mi < 4; mi++) {
                mma8(acc[mi][0], av[mi].x, av[mi].y, av[mi].z, av[mi].w, bv.x, bv.z);
                mma8(acc[mi][1], av[mi].x, av[mi].y, av[mi].z, av[mi].w, bv.y, bv.w);
            }
        }
        __syncthreads();
    }

    const int h = blockIdx.x, by = blockIdx.y;
#pragma unroll
    for (int mi = 0; mi < 4; mi++)
#pragma unroll
        for (int ni = 0; ni < 2; ni++)
#pragma unroll
            for (int e = 0; e < 4; e++) {
                int row = wm + mi * 16 + g + ((e >> 1) * 8);  // 0..127 (m rel)
                int col = wn + ni * 8 + t4 * 2 + (e & 1);     // 0..63  (d rel)
                uint32_t val = f2tf(acc[mi][ni][e]);
                int idx;
                if (z == 0) {
                    idx = (h * 16 + by) * 8192 + perm_word(8, row, col);
                } else {
                    int tile = by * 2 + (row >> 6);
                    int r64 = row & 63;
                    idx = (h * 32 + tile) * 4096 +
                          (z == 1 ? perm_word(8, r64, col) : perm_word(8, col, r64));
                }
                D[idx] = val;
            }
}

// ---------------------------------------------------------------------------
// Output projection: out = O @ Wo^T (plain layouts, fp32 in / tf32 mma).
// ---------------------------------------------------------------------------
__global__ __launch_bounds__(256) void gemm_out(const float* __restrict__ B,
                                                float* __restrict__ C) {
    __shared__ uint32_t Ap[4096];
    __shared__ uint32_t Bp[2048];
    const int tid = threadIdx.x, lane = tid & 31, wid = tid >> 5;
    const int g = lane >> 2, t4 = lane & 3;
    const int wm = (wid & 1) * 64, wn = (wid >> 1) * 16;
    const int m0 = blockIdx.y * 128, n0 = blockIdx.x * 64;
    const float* A = g_o;

    float acc[4][2][4] = {};
    float4 pa[4], pb[2];

#pragma unroll
    for (int i = 0; i < 4; i++) {
        int idx = tid + i * 256, r = idx >> 3, c4 = (idx & 7) * 4;
        pa[i] = *(const float4*)(A + (m0 + r) * DM + c4);
    }
#pragma unroll
    for (int i = 0; i < 2; i++) {
        int idx = tid + i * 256, r = idx >> 3, c4 = (idx & 7) * 4;
        pb[i] = *(const float4*)(B + (n0 + r) * DM + c4);
    }

    for (int kt = 0; kt < DM / 32; kt++) {
#pragma unroll
        for (int i = 0; i < 4; i++) {
            int idx = tid + i * 256, r = idx >> 3, c4 = (idx & 7) * 4;
            uint4 u = {f2tf(pa[i].x), f2tf(pa[i].y), f2tf(pa[i].z), f2tf(pa[i].w)};
            sts_perm4(Ap, 4, r, c4, u);
        }
#pragma unroll
        for (int i = 0; i < 2; i++) {
            int idx = tid + i * 256, r = idx >> 3, c4 = (idx & 7) * 4;
            uint4 u = {f2tf(pb[i].x), f2tf(pb[i].y), f2tf(pb[i].z), f2tf(pb[i].w)};
            sts_perm4(Bp, 4, r, c4, u);
        }
        __syncthreads();
        if (kt + 1 < DM / 32) {
            int k0 = (kt + 1) * 32;
#pragma unroll
            for (int i = 0; i < 4; i++) {
                int idx = tid + i * 256, r = idx >> 3, c4 = (idx & 7) * 4;
                pa[i] = *(const float4*)(A + (m0 + r) * DM + k0 + c4);
            }
#pragma unroll
            for (int i = 0; i < 2; i++) {
                int idx = tid + i * 256, r = idx >> 3, c4 = (idx & 7) * 4;
                pb[i] = *(const float4*)(B + (n0 + r) * DM + k0 + c4);
            }
        }
#pragma unroll
        for (int s = 0; s < 4; s++) {
            uint4 av[4];
#pragma unroll
            for (int mi = 0; mi < 4; mi++)
                av[mi] = *(const uint4*)&Ap[frag_addr(4, (wm >> 4) + mi, s, g, t4)];
            uint4 bv = *(const uint4*)&Bp[frag_addr(4, wn >> 4, s, g, t4)];
#pragma unroll
            for (int mi = 0; mi < 4; mi++) {
                mma8(acc[mi][0], av[mi].x, av[mi].y, av[mi].z, av[mi].w, bv.x, bv.z);
                mma8(acc[mi][1], av[mi].x, av[mi].y, av[mi].z, av[mi].w, bv.y, bv.w);
            }
        }
        __syncthreads();
    }

#pragma unroll
    for (int mi = 0; mi < 4; mi++)
#pragma unroll
        for (int ni = 0; ni < 2; ni++)
#pragma unroll
            for (int e = 0; e < 4; e++) {
                int row = m0 + wm + mi * 16 + g + (e >> 1) * 8;
                int col = n0 + wn + ni * 8 + t4 * 2 + (e & 1);
                C[row * DM + col] = acc[mi][ni][e];
            }
}

// ---------------------------------------------------------------------------
// Fused attention, cp.async pipelined. Per (head, 128-row block):
//   per 64-col tile: S=(QK^T)/8 masked -> STG pre-softmax attn + Sp smem,
//   O += S@V. K double-buffered (prefetch depth 1), V overlapped under S MMA.
// smem: Qp 32K | Kp0 16K | Kp1 16K | Vp 16K | Sp 32K = 112KB, 2 CTAs/SM.
// ---------------------------------------------------------------------------
__global__ __launch_bounds__(256, 2) void fused_attn(const int* __restrict__ mask,
                                                     float* __restrict__ attn) {
    extern __shared__ uint32_t sm[];
    uint32_t* Qp = sm;            // 8192 w
    uint32_t* Kp = sm + 8192;     // 2 x 4096 w
    uint32_t* Vp = sm + 16384;    // 4096 w
    uint32_t* Sp = sm + 20480;    // 8192 w

    const int tid = threadIdx.x, lane = tid & 31, wid = tid >> 5;
    const int g = lane >> 2, t4 = lane & 3;
    const int wm = (wid & 1) * 64, wn = (wid >> 1) * 16;
    const int h = blockIdx.y, mt = blockIdx.x;
    const int m0 = mt * 128;
    const size_t attn_base = (size_t)h * SQ * SQ;
    const uint32_t* kg = g_kp + h * 32 * 4096;
    const uint32_t* vg = g_vp + h * 32 * 4096;

    // prologue: start K[0], stage Q (linear copy, already permuted+tf32)
#pragma unroll
    for (int i = 0; i < 4; i++)
        cpa16(Kp + tid * 4 + i * 1024, kg + tid * 4 + i * 1024);
    CPA_COMMIT;
    {
        const uint32_t* qg = g_qp + (h * 16 + mt) * 8192;
#pragma unroll
        for (int i = 0; i < 8; i++) {
            uint4 u = *(const uint4*)(qg + tid * 4 + i * 1024);
            *(uint4*)(Qp + tid * 4 + i * 1024) = u;
        }
    }

    float oacc[4][2][4] = {};

    for (int tt = 0; tt < NT; tt++) {
        const int t0 = tt * 64;
        uint32_t* Kc = Kp + (tt & 1) * 4096;

        CPA_WAIT(0);       // K[tt] landed (issued prologue/last iter)
        __syncthreads();   // K visible to all; AV[tt-1] reads of Vp/Sp done

        // overlap V[tt] under S MMA; prefetch K[tt+1] under everything
#pragma unroll
        for (int i = 0; i < 4; i++)
            cpa16(Vp + tid * 4 + i * 1024, vg + tt * 4096 + tid * 4 + i * 1024);
        CPA_COMMIT;
        if (tt + 1 < NT) {
            uint32_t* Kn = Kp + ((tt + 1) & 1) * 4096;
#pragma unroll
            for (int i = 0; i < 4; i++)
                cpa16(Kn + tid * 4 + i * 1024, kg + (tt + 1) * 4096 + tid * 4 + i * 1024);
        }
        CPA_COMMIT;

        // S = Q K^T
        float sacc[4][2][4] = {};
#pragma unroll
        for (int s = 0; s < 8; s++) {
            uint4 aq[4];
#pragma unroll
            for (int mi = 0; mi < 4; mi++)
                aq[mi] = *(const uint4*)&Qp[frag_addr(8, (wm >> 4) + mi, s, g, t4)];
            uint4 bk = *(const uint4*)&Kc[frag_addr(8, wn >> 4, s, g, t4)];
#pragma unroll
            for (int mi = 0; mi < 4; mi++) {
                mma8(sacc[mi][0], aq[mi].x, aq[mi].y, aq[mi].z, aq[mi].w, bk.x, bk.z);
                mma8(sacc[mi][1], aq[mi].x, aq[mi].y, aq[mi].z, aq[mi].w, bk.y, bk.w);
            }
        }

        // epilogue: scale + mask, STG pre-softmax S, STS Sp (tf32)
#pragma unroll
        for (int mi = 0; mi < 4; mi++)
#pragma unroll
            for (int ni = 0; ni < 2; ni++)
#pragma unroll
                for (int e2 = 0; e2 < 2; e2++) {
                    int rl = wm + mi * 16 + g + e2 * 8;
                    int cl = wn + ni * 8 + t4 * 2;
                    int rg = m0 + rl, cg = t0 + cl;
                    int2 mk = *(const int2*)(mask + (size_t)rg * SQ + cg);
                    float v0 = sacc[mi][ni][e2 * 2] * 0.125f;
                    float v1 = sacc[mi][ni][e2 * 2 + 1] * 0.125f;
                    if (mk.x) v0 = -1e-7f;
                    if (mk.y) v1 = -1e-7f;
                    *(float2*)(attn + attn_base + (size_t)rg * SQ + cg) =
                        make_float2(v0, v1);
                    Sp[perm_word(8, rl, cl)] = f2tf(v0);
                    Sp[perm_word(8, rl, cl + 1)] = f2tf(v1);
                }

        CPA_WAIT(1);       // V[tt] landed (K[tt+1] may still be in flight)
        __syncthreads();   // Vp + Sp visible

        // O += S @ V
#pragma unroll
        for (int s = 0; s < 8; s++) {
            uint4 as[4];
#pragma unroll
            for (int mi = 0; mi < 4; mi++)
                as[mi] = *(const uint4*)&Sp[frag_addr(8, (wm >> 4) + mi, s, g, t4)];
            uint4 bv = *(const uint4*)&Vp[frag_addr(8, wn >> 4, s, g, t4)];
#pragma unroll
            for (int mi = 0; mi < 4; mi++) {
                mma8(oacc[mi][0], as[mi].x, as[mi].y, as[mi].z, as[mi].w, bv.x, bv.z);
                mma8(oacc[mi][1], as[mi].x, as[mi].y, as[mi].z, as[mi].w, bv.y, bv.w);
            }
        }
    }

#pragma unroll
    for (int mi = 0; mi < 4; mi++)
#pragma unroll
        for (int ni = 0; ni < 2; ni++)
#pragma unroll
            for (int e = 0; e < 4; e++) {
                int row = m0 + wm + mi * 16 + g + (e >> 1) * 8;
                int col = wn + ni * 8 + t4 * 2 + (e & 1);
                g_o[row * DM + h * HD + col] = oacc[mi][ni][e];
            }
}

// ---------------------------------------------------------------------------
// In-place row softmax (float4 vectorized). One block per row of attn [H*S, S].
// ---------------------------------------------------------------------------
__global__ void softmax_kernel(float* __restrict__ attn) {
    __shared__ float red[8];
    const size_t base = (size_t)blockIdx.x * SQ;
    const int tid = threadIdx.x;

    float4 v[2];
    v[0] = *(const float4*)(attn + base + tid * 4);
    v[1] = *(const float4*)(attn + base + 1024 + tid * 4);

    float m = fmaxf(fmaxf(fmaxf(v[0].x, v[0].y), fmaxf(v[0].z, v[0].w)),
                    fmaxf(fmaxf(v[1].x, v[1].y), fmaxf(v[1].z, v[1].w)));
#pragma unroll
    for (int o = 16; o; o >>= 1) m = fmaxf(m, __shfl_xor_sync(0xffffffffu, m, o));
    if ((tid & 31) == 0) red[tid >> 5] = m;
    __syncthreads();
    float mm = red[0];
#pragma unroll
    for (int w = 1; w < 8; w++) mm = fmaxf(mm, red[w]);

    float s = 0.f;
#pragma unroll
    for (int i = 0; i < 2; i++) {
        v[i].x = expf(v[i].x - mm); s += v[i].x;
        v[i].y = expf(v[i].y - mm); s += v[i].y;
        v[i].z = expf(v[i].z - mm); s += v[i].z;
        v[i].w = expf(v[i].w - mm); s += v[i].w;
    }
#pragma unroll
    for (int o = 16; o; o >>= 1) s += __shfl_xor_sync(0xffffffffu, s, o);
    __syncthreads();
    if ((tid & 31) == 0) red[tid >> 5] = s;
    __syncthreads();
    float ss = 0.f;
#pragma unroll
    for (int w = 0; w < 8; w++) ss += red[w];
    const float inv = 1.0f / ss;
#pragma unroll
    for (int i = 0; i < 2; i++) {
        v[i].x *= inv; v[i].y *= inv; v[i].z *= inv; v[i].w *= inv;
    }
    *(float4*)(attn + base + tid * 4) = v[0];
    *(float4*)(attn + base + 1024 + tid * 4) = v[1];
}

extern "C" void kernel_launch(void* const* d_in, const int* in_sizes, int n_in,
                              void* d_out, int out_size) {
    const float* q_in = (const float*)d_in[0];
    const float* k_in = (const float*)d_in[1];
    const float* v_in = (const float*)d_in[2];
    const int* mask = (const int*)d_in[3];
    const float* Wq = (const float*)d_in[4];
    const float* Wk = (const float*)d_in[5];
    const float* Wv = (const float*)d_in[6];
    const float* Wo = (const float*)d_in[7];

    float* out = (float*)d_out;           // [S, DM]
    float* attn = out + (size_t)SQ * DM;  // [H, S, S]

    static int smem_set = 0;
    if (!smem_set) {
        cudaFuncSetAttribute(fused_attn, cudaFuncAttributeMaxDynamicSharedMemorySize,
                             114688);
        smem_set = 1;
    }

    dim3 gQKV(DM / 64, SQ / 128, 3);  // (16, 16, 3)
    gemm_qkv<<<gQKV, 256>>>(q_in, k_in, v_in, Wq, Wk, Wv);

    dim3 gFused(SQ / 128, NH, 1);  // (16, 16)
    fused_attn<<<gFused, 256, 114688>>>(mask, attn);

    softmax_kernel<<<NH * SQ, 256>>>(attn);

    dim3 gOut(DM / 64, SQ / 128, 1);
    gemm_out<<<gOut, 256>>>(Wo, out);
}